// round 10
// baseline (speedup 1.0000x reference)
#include <cuda_runtime.h>
#include <cuda_bf16.h>
#include <math.h>
#include <stdint.h>

// Problem constants
#define BATCH 8
#define SEQ   2048
#define DMODEL 512

#define BM 256
#define BN 128
#define BKE 32                // bf16 k elements per chunk (two k16 steps)

// SW128-swizzled tiles: row = 128 B (hi bytes [0,64), lo bytes [64,128))
#define ATILE_B  32768        // 256 rows
#define BTILE_B  16384        // 128 rows
#define STAGE_B  (ATILE_B + BTILE_B)   // 48 KB
#define NSTAGE   4
#define DYN_SMEM (NSTAGE * STAGE_B)    // 192 KB

#define ICH 8                 // softmax i-chunks == SEQ/BM
#define MODE_PROJ   0
#define MODE_SCORES 1
#define MODE_AV     2

typedef __nv_bfloat16 bf16;
typedef __nv_bfloat162 bf162;

// ---------------------------------------------------------------------------
// Device scratch (allocation-guard-safe)
// ---------------------------------------------------------------------------
__device__ bf16 g_xhi[BATCH * SEQ * DMODEL], g_xlo[BATCH * SEQ * DMODEL];
__device__ bf16 g_Wthi[3 * DMODEL * DMODEL], g_Wtlo[3 * DMODEL * DMODEL];
__device__ bf16 g_Qhi[BATCH * SEQ * DMODEL], g_Qlo[BATCH * SEQ * DMODEL];
__device__ bf16 g_Khi[BATCH * SEQ * DMODEL], g_Klo[BATCH * SEQ * DMODEL];
__device__ bf16 g_Vhi[BATCH * SEQ * DMODEL], g_Vlo[BATCH * SEQ * DMODEL];
__device__ bf16 g_Vthi[BATCH * DMODEL * SEQ], g_Vtlo[BATCH * DMODEL * SEQ];
__device__ bf16 g_Whi[(long)BATCH * SEQ * SEQ], g_Wlo[(long)BATCH * SEQ * SEQ];
__device__ float g_pm[BATCH * ICH * SEQ], g_ps[BATCH * ICH * SEQ];
__device__ float g_gm[BATCH * SEQ], g_gi[BATCH * SEQ];

// ---------------------------------------------------------------------------
// PTX helpers
// ---------------------------------------------------------------------------
__device__ __forceinline__ uint32_t smem_u32(const void* p) {
    uint32_t a;
    asm("{ .reg .u64 t; cvta.to.shared.u64 t, %1; cvt.u32.u64 %0, t; }"
        : "=r"(a) : "l"(p));
    return a;
}
__device__ __forceinline__ void ldm_x4(uint32_t* r, uint32_t addr) {
    asm volatile("ldmatrix.sync.aligned.m8n8.x4.shared.b16 {%0,%1,%2,%3}, [%4];"
        : "=r"(r[0]), "=r"(r[1]), "=r"(r[2]), "=r"(r[3]) : "r"(addr));
}
__device__ __forceinline__ void mma16816(float* c, const uint32_t* a, const uint32_t* b) {
    asm volatile(
        "mma.sync.aligned.m16n8k16.row.col.f32.bf16.bf16.f32 "
        "{%0,%1,%2,%3}, {%4,%5,%6,%7}, {%8,%9}, {%0,%1,%2,%3};"
        : "+f"(c[0]), "+f"(c[1]), "+f"(c[2]), "+f"(c[3])
        : "r"(a[0]), "r"(a[1]), "r"(a[2]), "r"(a[3]), "r"(b[0]), "r"(b[1]));
}
__device__ __forceinline__ void cp16(uint32_t dst, const void* src) {
    asm volatile("cp.async.cg.shared.global [%0], [%1], 16;"
        :: "r"(dst), "l"(src) : "memory");
}
#define CP_COMMIT() asm volatile("cp.async.commit_group;" ::: "memory")
#define CP_WAIT0()  asm volatile("cp.async.wait_group 0;" ::: "memory")
#define CP_WAIT1()  asm volatile("cp.async.wait_group 1;" ::: "memory")

// ---------------------------------------------------------------------------
// cp.async tile load: ROWS x (32 bf16 hi + 32 bf16 lo) -> swizzled tile.
// 16B chunk c16 (0..7) of row r at r*128 + ((c16*16) ^ ((r&7)<<4)).
// ---------------------------------------------------------------------------
template<int ROWS>
__device__ __forceinline__ void cpa_tile(const bf16* __restrict__ hi,
                                         const bf16* __restrict__ lo,
                                         long ld, uint32_t base, int t)
{
    #pragma unroll
    for (int i = 0; i < ROWS / 64; i++) {
        const int ch = i * 256 + t;
        const int r = ch >> 2, c4 = ch & 3;
        cp16(base + r * 128 + (uint32_t)((c4 * 16) ^ ((r & 7) << 4)),
             (const char*)(hi + (long)r * ld) + c4 * 16);
    }
    #pragma unroll
    for (int i = 0; i < ROWS / 64; i++) {
        const int ch = i * 256 + t;
        const int r = ch >> 2, c4 = ch & 3;
        cp16(base + r * 128 + (uint32_t)(((c4 + 4) * 16) ^ ((r & 7) << 4)),
             (const char*)(lo + (long)r * ld) + c4 * 16);
    }
}

// ===========================================================================
// GEMM on pre-split bf16, 3-term split (hh + hl + lh), 4-stage pipeline.
// CTA tile 256x128, 256 threads (8 warps, 4 warp_m x 2 warp_n, 64x64 each).
// A: [M,K] K-major (hi/lo). B: [N,K] K-major (hi/lo). C = alpha * A @ B^T.
// ===========================================================================
template<int MODE>
__global__ __launch_bounds__(256, 1)
void gemm_ps(const bf16* __restrict__ Ahi, const bf16* __restrict__ Alo,
             const bf16* __restrict__ Bhi, const bf16* __restrict__ Blo,
             float alpha, int M, int N, int K, long sA, long sB, long sC,
             float* __restrict__ Cf,
             float* __restrict__ pm, float* __restrict__ ps,
             const float* __restrict__ bq, const float* __restrict__ bk,
             const float* __restrict__ bv,
             bf16* __restrict__ Qhi, bf16* __restrict__ Qlo,
             bf16* __restrict__ Khi, bf16* __restrict__ Klo,
             bf16* __restrict__ Vhi, bf16* __restrict__ Vlo)
{
    const long za = (long)blockIdx.z * sA;
    const long zb = (long)blockIdx.z * sB;
    const long zc = (long)blockIdx.z * sC;
    const int bm = blockIdx.y * BM;
    const int bn = blockIdx.x * BN;
    const int tid = threadIdx.x;
    const int wid = tid >> 5, lane = tid & 31;
    const int warp_m = wid & 3;    // 4 groups of 64 rows
    const int warp_n = wid >> 2;   // 2 groups of 64 cols

    extern __shared__ __align__(16) char dynsmem[];
    const uint32_t sbase = smem_u32(dynsmem);

    float acc[4][8][4] = {};   // [mi][ni][frag]

    // ldmatrix lane-address components
    const int a_row = warp_m * 64 + (lane & 15);
    const uint32_t a_k = (uint32_t)(((lane >> 4) * 8) * 2);
    const int b_row = warp_n * 64 + (lane & 7) + ((lane >> 4) * 8);
    const uint32_t b_k = (uint32_t)((((lane >> 3) & 1) * 8) * 2);
    const uint32_t swz = (uint32_t)((lane & 7) << 4);

    const bf16* Ah = Ahi + za + (long)bm * K;
    const bf16* Al = Alo + za + (long)bm * K;
    const bf16* Bh = Bhi + zb + (long)bn * K;
    const bf16* Bl = Blo + zb + (long)bn * K;

    const int nch = K / BKE;

    // Prologue: chunks 0 and 1
    cpa_tile<BM>(Ah, Al, K, sbase + 0 * STAGE_B, tid);
    cpa_tile<BN>(Bh, Bl, K, sbase + 0 * STAGE_B + ATILE_B, tid);
    CP_COMMIT();
    cpa_tile<BM>(Ah + BKE, Al + BKE, K, sbase + 1 * STAGE_B, tid);
    cpa_tile<BN>(Bh + BKE, Bl + BKE, K, sbase + 1 * STAGE_B + ATILE_B, tid);
    CP_COMMIT();

    int stage = 0;
    for (int c = 0; c < nch; c++) {
        if (c + 1 < nch) CP_WAIT1(); else CP_WAIT0();
        __syncthreads();

        // Prefetch chunk c+2 into stage (stage+2)%4 (readers done 2 chunks ago)
        if (c + 2 < nch) {
            int ns = stage + 2; if (ns >= NSTAGE) ns -= NSTAGE;
            const uint32_t nb = sbase + ns * STAGE_B;
            const long k0 = (long)(c + 2) * BKE;
            cpa_tile<BM>(Ah + k0, Al + k0, K, nb, tid);
            cpa_tile<BN>(Bh + k0, Bl + k0, K, nb + ATILE_B, tid);
            CP_COMMIT();
        }

        const uint32_t uA = sbase + stage * STAGE_B;
        const uint32_t uB = uA + ATILE_B;

        #pragma unroll
        for (int ks = 0; ks < 2; ks++) {
            const uint32_t akh = ((a_k + ks * 32) ^ swz);
            const uint32_t akl = ((a_k + ks * 32 + 64) ^ swz);
            const uint32_t bkh = ((b_k + ks * 32) ^ swz);
            const uint32_t bkl = ((b_k + ks * 32 + 64) ^ swz);
            uint32_t afh[4][4], afl[4][4], bfh[4][4], bfl[4][4];
            #pragma unroll
            for (int mi = 0; mi < 4; mi++)
                ldm_x4(afh[mi], uA + (uint32_t)((a_row + mi * 16) * 128) + akh);
            #pragma unroll
            for (int nb2 = 0; nb2 < 4; nb2++)
                ldm_x4(bfh[nb2], uB + (uint32_t)((b_row + nb2 * 16) * 128) + bkh);
            #pragma unroll
            for (int mi = 0; mi < 4; mi++)
                #pragma unroll
                for (int ni = 0; ni < 8; ni++)
                    mma16816(acc[mi][ni], afh[mi], &bfh[ni >> 1][(ni & 1) * 2]);
            #pragma unroll
            for (int nb2 = 0; nb2 < 4; nb2++)
                ldm_x4(bfl[nb2], uB + (uint32_t)((b_row + nb2 * 16) * 128) + bkl);
            #pragma unroll
            for (int mi = 0; mi < 4; mi++)
                #pragma unroll
                for (int ni = 0; ni < 8; ni++)
                    mma16816(acc[mi][ni], afh[mi], &bfl[ni >> 1][(ni & 1) * 2]);
            #pragma unroll
            for (int mi = 0; mi < 4; mi++)
                ldm_x4(afl[mi], uA + (uint32_t)((a_row + mi * 16) * 128) + akl);
            #pragma unroll
            for (int mi = 0; mi < 4; mi++)
                #pragma unroll
                for (int ni = 0; ni < 8; ni++)
                    mma16816(acc[mi][ni], afl[mi], &bfh[ni >> 1][(ni & 1) * 2]);
        }
        stage = stage + 1; if (stage >= NSTAGE) stage = 0;
    }

    // ---------------- Epilogue ----------------
    const int erow = lane >> 2;
    const int ecol = 2 * (lane & 3);

    if (MODE == MODE_PROJ) {
        #pragma unroll
        for (int mi = 0; mi < 4; mi++) {
            #pragma unroll
            for (int ni = 0; ni < 8; ni++) {
                const int col = bn + warp_n * 64 + ni * 8 + ecol;
                const int sel = col >> 9;
                const int nn = col & 511;
                const float* bp = (sel == 0) ? bq : (sel == 1) ? bk : bv;
                bf16* ph = (sel == 0) ? Qhi : (sel == 1) ? Khi : Vhi;
                bf16* pl = (sel == 0) ? Qlo : (sel == 1) ? Klo : Vlo;
                const float bx = bp[nn], by = bp[nn + 1];
                #pragma unroll
                for (int h = 0; h < 2; h++) {
                    const int row = bm + warp_m * 64 + mi * 16 + erow + h * 8;
                    float vx = acc[mi][ni][2 * h + 0] + bx;
                    float vy = acc[mi][ni][2 * h + 1] + by;
                    const long off = (long)row * DMODEL + nn;
                    bf162 hh = __floats2bfloat162_rn(vx, vy);
                    float2 hf = __bfloat1622float2(hh);
                    bf162 ll = __floats2bfloat162_rn(vx - hf.x, vy - hf.y);
                    *(bf162*)(ph + off) = hh;
                    *(bf162*)(pl + off) = ll;
                }
            }
        }
    } else {
        #pragma unroll
        for (int mi = 0; mi < 4; mi++) {
            #pragma unroll
            for (int ni = 0; ni < 8; ni++) {
                const int col = bn + warp_n * 64 + ni * 8 + ecol;
                #pragma unroll
                for (int h = 0; h < 2; h++) {
                    const int row = bm + warp_m * 64 + mi * 16 + erow + h * 8;
                    float2 v;
                    v.x = acc[mi][ni][2 * h + 0] * alpha;
                    v.y = acc[mi][ni][2 * h + 1] * alpha;
                    *(float2*)(Cf + zc + (long)row * N + col) = v;
                }
            }
        }
    }

    if (MODE == MODE_SCORES) {
        // Column softmax partials over this CTA's 256 rows.
        __syncthreads();                              // smem reuse
        float* red_m = (float*)dynsmem;               // [4][128]
        float* red_s = (float*)(dynsmem + 2048);      // [4][128]

        float lm[8][2];
        #pragma unroll
        for (int ni = 0; ni < 8; ni++)
            #pragma unroll
            for (int cc = 0; cc < 2; cc++) {
                float m = -INFINITY;
                #pragma unroll
                for (int mi = 0; mi < 4; mi++)
                    #pragma unroll
                    for (int h = 0; h < 2; h++)
                        m = fmaxf(m, acc[mi][ni][2 * h + cc] * alpha);
                lm[ni][cc] = m;
            }
        #pragma unroll
        for (int off = 4; off < 32; off <<= 1)
            #pragma unroll
            for (int ni = 0; ni < 8; ni++)
                #pragma unroll
                for (int cc = 0; cc < 2; cc++)
                    lm[ni][cc] = fmaxf(lm[ni][cc],
                        __shfl_xor_sync(0xffffffffu, lm[ni][cc], off));
        if (lane < 4) {
            #pragma unroll
            for (int ni = 0; ni < 8; ni++)
                #pragma unroll
                for (int cc = 0; cc < 2; cc++)
                    red_m[warp_m * 128 + warp_n * 64 + ni * 8 + 2 * lane + cc] = lm[ni][cc];
        }
        __syncthreads();

        float cmax[8][2], lsum[8][2];
        #pragma unroll
        for (int ni = 0; ni < 8; ni++)
            #pragma unroll
            for (int cc = 0; cc < 2; cc++) {
                const int cl = warp_n * 64 + ni * 8 + ecol + cc;
                float m = red_m[cl];
                m = fmaxf(m, red_m[128 + cl]);
                m = fmaxf(m, red_m[256 + cl]);
                m = fmaxf(m, red_m[384 + cl]);
                cmax[ni][cc] = m;
                float s = 0.f;
                #pragma unroll
                for (int mi = 0; mi < 4; mi++)
                    #pragma unroll
                    for (int h = 0; h < 2; h++)
                        s += __expf(acc[mi][ni][2 * h + cc] * alpha - m);
                lsum[ni][cc] = s;
            }
        #pragma unroll
        for (int off = 4; off < 32; off <<= 1)
            #pragma unroll
            for (int ni = 0; ni < 8; ni++)
                #pragma unroll
                for (int cc = 0; cc < 2; cc++)
                    lsum[ni][cc] += __shfl_xor_sync(0xffffffffu, lsum[ni][cc], off);
        if (lane < 4) {
            #pragma unroll
            for (int ni = 0; ni < 8; ni++)
                #pragma unroll
                for (int cc = 0; cc < 2; cc++)
                    red_s[warp_m * 128 + warp_n * 64 + ni * 8 + 2 * lane + cc] = lsum[ni][cc];
        }
        __syncthreads();

        if (warp_m == 0 && lane < 4) {
            const long pbase = ((long)blockIdx.z * ICH + blockIdx.y) * SEQ + bn;
            #pragma unroll
            for (int ni = 0; ni < 8; ni++)
                #pragma unroll
                for (int cc = 0; cc < 2; cc++) {
                    const int cl = warp_n * 64 + ni * 8 + 2 * lane + cc;
                    pm[pbase + cl] = cmax[ni][cc];
                    ps[pbase + cl] = red_s[cl] + red_s[128 + cl]
                                   + red_s[256 + cl] + red_s[384 + cl];
                }
        }
    }
}

// ---------------------------------------------------------------------------
// fp32 -> hi/lo bf16 elementwise (vectorized by 4)
// ---------------------------------------------------------------------------
__global__ void split_fp32(const float* __restrict__ src,
                           bf16* __restrict__ hi, bf16* __restrict__ lo, long n4)
{
    const long i = (long)blockIdx.x * blockDim.x + threadIdx.x;
    if (i >= n4) return;
    float4 a = ((const float4*)src)[i];
    bf162 h0 = __floats2bfloat162_rn(a.x, a.y);
    bf162 h1 = __floats2bfloat162_rn(a.z, a.w);
    float2 f0 = __bfloat1622float2(h0);
    float2 f1 = __bfloat1622float2(h1);
    bf162 l0 = __floats2bfloat162_rn(a.x - f0.x, a.y - f0.y);
    bf162 l1 = __floats2bfloat162_rn(a.z - f1.x, a.w - f1.y);
    ((bf162*)hi)[2 * i] = h0; ((bf162*)hi)[2 * i + 1] = h1;
    ((bf162*)lo)[2 * i] = l0; ((bf162*)lo)[2 * i + 1] = l1;
}

// ---------------------------------------------------------------------------
// Transpose + split: W fp32 [K=512][N=512] -> Wt split bf16 [n][k]; grid.z = which W
// ---------------------------------------------------------------------------
__global__ void transpose_split_w(const float* __restrict__ W0,
                                  const float* __restrict__ W1,
                                  const float* __restrict__ W2,
                                  bf16* __restrict__ Thi, bf16* __restrict__ Tlo)
{
    __shared__ float tile[32][33];
    const int w = blockIdx.z;
    const float* W = (w == 0) ? W0 : (w == 1) ? W1 : W2;
    bf16* th = Thi + (long)w * DMODEL * DMODEL;
    bf16* tl = Tlo + (long)w * DMODEL * DMODEL;
    const int k0 = blockIdx.y * 32, n0 = blockIdx.x * 32;
    const int tx = threadIdx.x, ty = threadIdx.y;
    #pragma unroll
    for (int yy = 0; yy < 32; yy += 8)
        tile[ty + yy][tx] = W[(long)(k0 + ty + yy) * DMODEL + n0 + tx];
    __syncthreads();
    #pragma unroll
    for (int yy = 0; yy < 32; yy += 8) {
        float v = tile[tx][ty + yy];
        bf16 h = __float2bfloat16_rn(v);
        bf16 l = __float2bfloat16_rn(v - __bfloat162float(h));
        th[(long)(n0 + ty + yy) * DMODEL + k0 + tx] = h;
        tl[(long)(n0 + ty + yy) * DMODEL + k0 + tx] = l;
    }
}

// ---------------------------------------------------------------------------
// Transpose split-bf16 V [b*N + n][e] -> Vt [b][e][n]
// ---------------------------------------------------------------------------
__global__ void transpose_v(const bf16* __restrict__ Vhi, const bf16* __restrict__ Vlo,
                            bf16* __restrict__ Thi, bf16* __restrict__ Tlo)
{
    __shared__ bf16 th[32][33], tl[32][33];
    const long b = blockIdx.z;
    const int e0 = blockIdx.x * 32, n0 = blockIdx.y * 32;
    const int tx = threadIdx.x, ty = threadIdx.y;
    #pragma unroll
    for (int yy = 0; yy < 32; yy += 8) {
        const long src = (b * SEQ + n0 + ty + yy) * DMODEL + e0 + tx;
        th[ty + yy][tx] = Vhi[src];
        tl[ty + yy][tx] = Vlo[src];
    }
    __syncthreads();
    #pragma unroll
    for (int yy = 0; yy < 32; yy += 8) {
        const long dst = b * DMODEL * SEQ + (long)(e0 + ty + yy) * SEQ + n0 + tx;
        Thi[dst] = th[tx][ty + yy];
        Tlo[dst] = tl[tx][ty + yy];
    }
}

// ---------------------------------------------------------------------------
// Softmax combine + normalize
// ---------------------------------------------------------------------------
__global__ void sm_pass2(const float* __restrict__ pm, const float* __restrict__ ps,
                         float* __restrict__ gm, float* __restrict__ gi)
{
    const int j = blockIdx.x * blockDim.x + threadIdx.x;
    const long b = blockIdx.y;
    float m = -INFINITY;
    #pragma unroll
    for (int ic = 0; ic < ICH; ic++)
        m = fmaxf(m, pm[(b * ICH + ic) * SEQ + j]);
    float s = 0.0f;
    #pragma unroll
    for (int ic = 0; ic < ICH; ic++)
        s += ps[(b * ICH + ic) * SEQ + j] * __expf(pm[(b * ICH + ic) * SEQ + j] - m);
    gm[b * SEQ + j] = m;
    gi[b * SEQ + j] = 1.0f / s;
}

__global__ void sm_pass3(float* __restrict__ S,
                         const float* __restrict__ gm, const float* __restrict__ gi,
                         bf16* __restrict__ whi, bf16* __restrict__ wlo)
{
    const int j4 = (blockIdx.x * blockDim.x + threadIdx.x) * 4;
    const int i = blockIdx.y;
    const long b = blockIdx.z;
    const long off = b * (long)SEQ * SEQ + (long)i * SEQ + j4;
    float4 x = *(const float4*)(S + off);
    float4 m = *(const float4*)(gm + b * SEQ + j4);
    float4 v = *(const float4*)(gi + b * SEQ + j4);
    float4 w;
    w.x = __expf(x.x - m.x) * v.x;
    w.y = __expf(x.y - m.y) * v.y;
    w.z = __expf(x.z - m.z) * v.z;
    w.w = __expf(x.w - m.w) * v.w;
    *(float4*)(S + off) = w;
    bf162 h0 = __floats2bfloat162_rn(w.x, w.y);
    bf162 h1 = __floats2bfloat162_rn(w.z, w.w);
    float2 f0 = __bfloat1622float2(h0);
    float2 f1 = __bfloat1622float2(h1);
    bf162 l0 = __floats2bfloat162_rn(w.x - f0.x, w.y - f0.y);
    bf162 l1 = __floats2bfloat162_rn(w.z - f1.x, w.w - f1.y);
    *(bf162*)(whi + off) = h0; *(bf162*)(whi + off + 2) = h1;
    *(bf162*)(wlo + off) = l0; *(bf162*)(wlo + off + 2) = l1;
}

// ---------------------------------------------------------------------------
// kernel_launch
// ---------------------------------------------------------------------------
extern "C" void kernel_launch(void* const* d_in, const int* in_sizes, int n_in,
                              void* d_out, int out_size)
{
    const float* x  = (const float*)d_in[0];
    const float* Wq = (const float*)d_in[1];
    const float* bq = (const float*)d_in[2];
    const float* Wk = (const float*)d_in[3];
    const float* bk = (const float*)d_in[4];
    const float* Wv = (const float*)d_in[5];
    const float* bv = (const float*)d_in[6];

    float* out     = (float*)d_out;
    float* weights = out + (long)BATCH * SEQ * DMODEL;

    bf16 *xhi, *xlo, *Wthi, *Wtlo, *Qhi, *Qlo, *Khi, *Klo, *Vhi, *Vlo;
    bf16 *Vthi, *Vtlo, *Whi, *Wlo;
    float *pm, *ps, *gm, *gi;
    cudaGetSymbolAddress((void**)&xhi, g_xhi);   cudaGetSymbolAddress((void**)&xlo, g_xlo);
    cudaGetSymbolAddress((void**)&Wthi, g_Wthi); cudaGetSymbolAddress((void**)&Wtlo, g_Wtlo);
    cudaGetSymbolAddress((void**)&Qhi, g_Qhi);   cudaGetSymbolAddress((void**)&Qlo, g_Qlo);
    cudaGetSymbolAddress((void**)&Khi, g_Khi);   cudaGetSymbolAddress((void**)&Klo, g_Klo);
    cudaGetSymbolAddress((void**)&Vhi, g_Vhi);   cudaGetSymbolAddress((void**)&Vlo, g_Vlo);
    cudaGetSymbolAddress((void**)&Vthi, g_Vthi); cudaGetSymbolAddress((void**)&Vtlo, g_Vtlo);
    cudaGetSymbolAddress((void**)&Whi, g_Whi);   cudaGetSymbolAddress((void**)&Wlo, g_Wlo);
    cudaGetSymbolAddress((void**)&pm, g_pm);     cudaGetSymbolAddress((void**)&ps, g_ps);
    cudaGetSymbolAddress((void**)&gm, g_gm);     cudaGetSymbolAddress((void**)&gi, g_gi);

    static bool attr_set = false;
    if (!attr_set) {
        cudaFuncSetAttribute(gemm_ps<MODE_PROJ>,
                             cudaFuncAttributeMaxDynamicSharedMemorySize, DYN_SMEM);
        cudaFuncSetAttribute(gemm_ps<MODE_SCORES>,
                             cudaFuncAttributeMaxDynamicSharedMemorySize, DYN_SMEM);
        cudaFuncSetAttribute(gemm_ps<MODE_AV>,
                             cudaFuncAttributeMaxDynamicSharedMemorySize, DYN_SMEM);
        attr_set = true;
    }

    const dim3 blk(256);
    const long MD = (long)BATCH * SEQ * DMODEL;

    // 0) split inputs
    split_fp32<<<(unsigned)((MD / 4 + 255) / 256), blk>>>(x, xhi, xlo, MD / 4);
    {
        dim3 g(16, 16, 3), b(32, 8);
        transpose_split_w<<<g, b>>>(Wq, Wk, Wv, Wthi, Wtlo);
    }

    // 1) fused QKV projection: [16384, 1536] = x @ [Wq|Wk|Wv]^T, split outputs
    {
        dim3 grid(3 * DMODEL / BN, (BATCH * SEQ) / BM, 1);
        gemm_ps<MODE_PROJ><<<grid, blk, DYN_SMEM>>>(xhi, xlo, Wthi, Wtlo,
            1.0f, BATCH * SEQ, 3 * DMODEL, DMODEL, 0, 0, 0,
            nullptr, nullptr, nullptr, bq, bk, bv,
            Qhi, Qlo, Khi, Klo, Vhi, Vlo);
    }

    // 1b) V -> Vt (per batch [e][n])
    {
        dim3 g(DMODEL / 32, SEQ / 32, BATCH), b(32, 8);
        transpose_v<<<g, b>>>(Vhi, Vlo, Vthi, Vtlo);
    }

    // 2) scores = scale * Q @ K^T -> weights (fp32) + softmax partials
    {
        const float scale = 1.0f / sqrtf((float)DMODEL);
        dim3 grid(SEQ / BN, SEQ / BM, BATCH);
        gemm_ps<MODE_SCORES><<<grid, blk, DYN_SMEM>>>(Qhi, Qlo, Khi, Klo,
            scale, SEQ, SEQ, DMODEL,
            (long)SEQ * DMODEL, (long)SEQ * DMODEL, (long)SEQ * SEQ,
            weights, pm, ps, nullptr, nullptr, nullptr,
            nullptr, nullptr, nullptr, nullptr, nullptr, nullptr);
    }

    // 3) softmax combine + normalize (pass3 also emits split bf16 weights)
    {
        dim3 g2(SEQ / 256, BATCH);
        sm_pass2<<<g2, blk>>>(pm, ps, gm, gi);
        dim3 g3(SEQ / (256 * 4), SEQ, BATCH);
        sm_pass3<<<g3, blk>>>(weights, gm, gi, Whi, Wlo);
    }

    // 4) out = weights @ V  (B = Vt [e][j], K-major over j)
    {
        dim3 grid(DMODEL / BN, SEQ / BM, BATCH);
        gemm_ps<MODE_AV><<<grid, blk, DYN_SMEM>>>(Whi, Wlo, Vthi, Vtlo,
            1.0f, SEQ, DMODEL, SEQ,
            (long)SEQ * SEQ, (long)DMODEL * SEQ, (long)SEQ * DMODEL,
            out, nullptr, nullptr, nullptr, nullptr, nullptr,
            nullptr, nullptr, nullptr, nullptr, nullptr, nullptr);
    }
}

// round 11
// speedup vs baseline: 1.2563x; 1.2563x over previous
#include <cuda_runtime.h>
#include <cuda_bf16.h>
#include <math.h>
#include <stdint.h>

// Problem constants
#define BATCH 8
#define SEQ   2048
#define DMODEL 512

#define BM 128
#define BN 128
// tile: 128 rows x 128B (hi bytes [0,64), lo [64,128)), XOR-swizzled, = 16KB
#define TILE_B  16384
#define STAGE_B (2 * TILE_B)
#define NSTAGE  3
#define DYN_SMEM (NSTAGE * STAGE_B)   // 96 KB

#define ICH 16
#define MODE_PROJ   0
#define MODE_SCORES 1
#define MODE_AV     2

typedef __nv_bfloat16 bf16;
typedef __nv_bfloat162 bf162;

// ---------------------------------------------------------------------------
// Device scratch: panel (tile-major, pre-swizzled) arrays hold hi+lo combined
// (2 bf16 per logical element). V kept linear for the transpose.
// ---------------------------------------------------------------------------
__device__ bf16 g_x[(long)BATCH * SEQ * DMODEL * 2];        // panels, KC=16
__device__ bf16 g_Wt[3L * DMODEL * DMODEL * 2];             // panels, KC=16
__device__ bf16 g_Q[(long)BATCH * SEQ * DMODEL * 2];        // panels, KC=16
__device__ bf16 g_K[(long)BATCH * SEQ * DMODEL * 2];        // panels, KC=16
__device__ bf16 g_Vhi[(long)BATCH * SEQ * DMODEL];          // linear
__device__ bf16 g_Vlo[(long)BATCH * SEQ * DMODEL];          // linear
__device__ bf16 g_Vt[(long)BATCH * DMODEL * SEQ * 2];       // panels, KC=64
__device__ bf16 g_W[(long)BATCH * SEQ * SEQ * 2];           // panels, KC=64
__device__ float g_pm[BATCH * ICH * SEQ], g_ps[BATCH * ICH * SEQ];
__device__ float g_gm[BATCH * SEQ], g_gi[BATCH * SEQ];

// ---------------------------------------------------------------------------
// Panel addressing: tile(p) at byte p*16384; element (r, kk) r in [0,128),
// kk in [0,32): hi at r*128 + ((kk>>3)*16 ^ ((r&7)<<4)) + (kk&7)*2,
// lo at chunk index (kk>>3)+4.
// ---------------------------------------------------------------------------
__device__ __forceinline__ uint32_t off_hi(int r, int kk) {
    return (uint32_t)((r << 7) + ((((kk >> 3) << 4) ^ ((r & 7) << 4)) | ((kk & 7) << 1)));
}
__device__ __forceinline__ uint32_t off_lo(int r, int kk) {
    return (uint32_t)((r << 7) + (((((kk >> 3) + 4) << 4) ^ ((r & 7) << 4)) | ((kk & 7) << 1)));
}

// ---------------------------------------------------------------------------
// PTX helpers
// ---------------------------------------------------------------------------
__device__ __forceinline__ uint32_t smem_u32(const void* p) {
    uint32_t a;
    asm("{ .reg .u64 t; cvta.to.shared.u64 t, %1; cvt.u32.u64 %0, t; }"
        : "=r"(a) : "l"(p));
    return a;
}
__device__ __forceinline__ void ldm_x4(uint32_t* r, uint32_t addr) {
    asm volatile("ldmatrix.sync.aligned.m8n8.x4.shared.b16 {%0,%1,%2,%3}, [%4];"
        : "=r"(r[0]), "=r"(r[1]), "=r"(r[2]), "=r"(r[3]) : "r"(addr));
}
__device__ __forceinline__ void mma16816(float* c, const uint32_t* a, const uint32_t* b) {
    asm volatile(
        "mma.sync.aligned.m16n8k16.row.col.f32.bf16.bf16.f32 "
        "{%0,%1,%2,%3}, {%4,%5,%6,%7}, {%8,%9}, {%0,%1,%2,%3};"
        : "+f"(c[0]), "+f"(c[1]), "+f"(c[2]), "+f"(c[3])
        : "r"(a[0]), "r"(a[1]), "r"(a[2]), "r"(a[3]), "r"(b[0]), "r"(b[1]));
}

#define MBARRIER_INIT(addr, cnt) \
    asm volatile("mbarrier.init.shared.b64 [%0], %1;" \
                 :: "r"((uint32_t)(addr)), "r"((uint32_t)(cnt)) : "memory")
#define MBARRIER_EXPECT_TX(addr, bytes) \
    asm volatile("mbarrier.arrive.expect_tx.shared.b64 _, [%0], %1;" \
                 :: "r"((uint32_t)(addr)), "r"((uint32_t)(bytes)) : "memory")
#define CP_BULK(dst, src, bytes, bar) \
    asm volatile("cp.async.bulk.shared::cta.global.mbarrier::complete_tx::bytes " \
                 "[%0], [%1], %2, [%3];" \
                 :: "r"((uint32_t)(dst)), "l"(src), "r"((uint32_t)(bytes)), \
                    "r"((uint32_t)(bar)) : "memory")
#define FENCE_PROXY_ASYNC() \
    asm volatile("fence.proxy.async.shared::cta;" ::: "memory")

#define MBARRIER_WAIT_PARITY(mbar_smem_addr, phase_parity) do { \
    uint32_t _mbar = (uint32_t)(mbar_smem_addr); \
    uint32_t _parity = (uint32_t)(phase_parity); \
    uint32_t _done; \
    asm volatile( \
        "{\n\t.reg .pred p;\n\t" \
        "mbarrier.try_wait.parity.acquire.cta.shared::cta.b64 p, [%1], %2;\n\t" \
        "selp.b32 %0, 1, 0, p;\n\t}" \
        : "=r"(_done) : "r"(_mbar), "r"(_parity) : "memory"); \
    if (!_done) { \
        asm volatile( \
            "{\n\t.reg .pred P1;\n\t" \
            "WAIT_LOOP_%=:\n\t" \
            "mbarrier.try_wait.parity.acquire.cta.shared::cta.b64 P1, [%0], %1, 0x989680;\n\t" \
            "@P1 bra.uni WAIT_DONE_%=;\n\t" \
            "bra.uni WAIT_LOOP_%=;\n\t" \
            "WAIT_DONE_%=:\n\t}" \
            :: "r"(_mbar), "r"(_parity) : "memory"); \
    } \
} while(0)

// ===========================================================================
// GEMM on panel-layout split bf16, 3-term split (hh+hl+lh).
// Tiles fetched with cp.async.bulk (16KB each) into a 3-stage smem ring.
// CTA tile 128x128, 256 threads (2 warp_m x 4 warp_n, 64x32 warp tiles).
// ===========================================================================
template<int MODE>
__global__ __launch_bounds__(256, 2)
void gemm_ps(const char* __restrict__ Ab, const char* __restrict__ Bb,
             float alpha, int N, int KC, long sA, long sB, long sC,
             float* __restrict__ Cf,
             float* __restrict__ pm, float* __restrict__ ps,
             const float* __restrict__ bq, const float* __restrict__ bk,
             const float* __restrict__ bv,
             bf16* __restrict__ Qp, bf16* __restrict__ Kp,
             bf16* __restrict__ Vhi, bf16* __restrict__ Vlo)
{
    const char* A = Ab + (long)blockIdx.z * sA;
    const char* B = Bb + (long)blockIdx.z * sB;
    const long zc = (long)blockIdx.z * sC;
    const int bm = blockIdx.y * BM;
    const int bn = blockIdx.x * BN;
    const int tid = threadIdx.x;
    const int wid = tid >> 5, lane = tid & 31;
    const int warp_m = wid & 1;
    const int warp_n = wid >> 1;

    extern __shared__ __align__(16) char dynsmem[];
    const uint32_t sbase = smem_u32(dynsmem);
    __shared__ __align__(8) unsigned long long s_bar[NSTAGE];
    const uint32_t bar0 = smem_u32(s_bar);

    if (tid == 0) {
        #pragma unroll
        for (int s = 0; s < NSTAGE; s++) MBARRIER_INIT(bar0 + s * 8, 1);
        FENCE_PROXY_ASYNC();
    }
    __syncthreads();

    float acc[4][4][4] = {};

    const int a_row = warp_m * 64 + (lane & 15);
    const uint32_t a_k = (uint32_t)(((lane >> 4) * 8) * 2);
    const int b_row = warp_n * 32 + (lane & 7) + ((lane >> 4) * 8);
    const uint32_t b_k = (uint32_t)((((lane >> 3) & 1) * 8) * 2);
    const uint32_t swz = (uint32_t)((lane & 7) << 4);

    const int nch = KC;
    const long pA = (long)blockIdx.y * KC;   // A panel row-block
    const long pB = (long)blockIdx.x * KC;

    // Prologue: issue chunks 0 and 1
    if (tid == 0) {
        #pragma unroll
        for (int c = 0; c < 2; c++) {
            const uint32_t bar = bar0 + c * 8;
            MBARRIER_EXPECT_TX(bar, 2 * TILE_B);
            CP_BULK(sbase + c * STAGE_B,          A + ((pA + c) << 14), TILE_B, bar);
            CP_BULK(sbase + c * STAGE_B + TILE_B, B + ((pB + c) << 14), TILE_B, bar);
        }
    }

    for (int c = 0; c < nch; c++) {
        // Issue chunk c+2 into stage (c+2)%3 (its previous use finished at c-1)
        if (tid == 0 && c + 2 < nch) {
            const int s = (c + 2) % NSTAGE;
            const uint32_t bar = bar0 + s * 8;
            MBARRIER_EXPECT_TX(bar, 2 * TILE_B);
            CP_BULK(sbase + s * STAGE_B,          A + ((pA + c + 2) << 14), TILE_B, bar);
            CP_BULK(sbase + s * STAGE_B + TILE_B, B + ((pB + c + 2) << 14), TILE_B, bar);
        }

        const int st = c % NSTAGE;
        MBARRIER_WAIT_PARITY(bar0 + st * 8, (c / NSTAGE) & 1);

        const uint32_t uA = sbase + st * STAGE_B;
        const uint32_t uB = uA + TILE_B;

        #pragma unroll
        for (int ks = 0; ks < 2; ks++) {
            const uint32_t akh = ((a_k + ks * 32) ^ swz);
            const uint32_t akl = ((a_k + ks * 32 + 64) ^ swz);
            const uint32_t bkh = ((b_k + ks * 32) ^ swz);
            const uint32_t bkl = ((b_k + ks * 32 + 64) ^ swz);
            uint32_t afh[4][4], afl[4][4], bfh[2][4], bfl[2][4];
            #pragma unroll
            for (int mi = 0; mi < 4; mi++)
                ldm_x4(afh[mi], uA + (uint32_t)((a_row + mi * 16) * 128) + akh);
            #pragma unroll
            for (int nb2 = 0; nb2 < 2; nb2++)
                ldm_x4(bfh[nb2], uB + (uint32_t)((b_row + nb2 * 16) * 128) + bkh);
            #pragma unroll
            for (int mi = 0; mi < 4; mi++)
                #pragma unroll
                for (int ni = 0; ni < 4; ni++)
                    mma16816(acc[mi][ni], afh[mi], &bfh[ni >> 1][(ni & 1) * 2]);
            #pragma unroll
            for (int nb2 = 0; nb2 < 2; nb2++)
                ldm_x4(bfl[nb2], uB + (uint32_t)((b_row + nb2 * 16) * 128) + bkl);
            #pragma unroll
            for (int mi = 0; mi < 4; mi++)
                #pragma unroll
                for (int ni = 0; ni < 4; ni++)
                    mma16816(acc[mi][ni], afh[mi], &bfl[ni >> 1][(ni & 1) * 2]);
            #pragma unroll
            for (int mi = 0; mi < 4; mi++)
                ldm_x4(afl[mi], uA + (uint32_t)((a_row + mi * 16) * 128) + akl);
            #pragma unroll
            for (int mi = 0; mi < 4; mi++)
                #pragma unroll
                for (int ni = 0; ni < 4; ni++)
                    mma16816(acc[mi][ni], afl[mi], &bfh[ni >> 1][(ni & 1) * 2]);
        }
        __syncthreads();   // all readers done before stage is re-armed
    }

    // ---------------- Epilogue ----------------
    const int erow = lane >> 2;
    const int ecol = 2 * (lane & 3);

    if (MODE == MODE_PROJ) {
        #pragma unroll
        for (int mi = 0; mi < 4; mi++) {
            #pragma unroll
            for (int ni = 0; ni < 4; ni++) {
                const int col = bn + warp_n * 32 + ni * 8 + ecol;
                const int sel = col >> 9;
                const int nn = col & 511;
                const float* bp = (sel == 0) ? bq : (sel == 1) ? bk : bv;
                const float bx = bp[nn], by = bp[nn + 1];
                #pragma unroll
                for (int h = 0; h < 2; h++) {
                    const int row = bm + warp_m * 64 + mi * 16 + erow + h * 8;
                    float vx = acc[mi][ni][2 * h + 0] + bx;
                    float vy = acc[mi][ni][2 * h + 1] + by;
                    bf162 hh = __floats2bfloat162_rn(vx, vy);
                    float2 hf = __bfloat1622float2(hh);
                    bf162 ll = __floats2bfloat162_rn(vx - hf.x, vy - hf.y);
                    if (sel == 2) {
                        const long off = (long)row * DMODEL + nn;
                        *(bf162*)(Vhi + off) = hh;
                        *(bf162*)(Vlo + off) = ll;
                    } else {
                        char* basep = (char*)((sel == 0) ? Qp : Kp);
                        const long pnl = (long)(row >> 7) * 16 + (nn >> 5);
                        const int r = row & 127, kk = nn & 31;
                        *(bf162*)(basep + (pnl << 14) + off_hi(r, kk)) = hh;
                        *(bf162*)(basep + (pnl << 14) + off_lo(r, kk)) = ll;
                    }
                }
            }
        }
    } else {
        #pragma unroll
        for (int mi = 0; mi < 4; mi++) {
            #pragma unroll
            for (int ni = 0; ni < 4; ni++) {
                const int col = bn + warp_n * 32 + ni * 8 + ecol;
                #pragma unroll
                for (int h = 0; h < 2; h++) {
                    const int row = bm + warp_m * 64 + mi * 16 + erow + h * 8;
                    float2 v;
                    v.x = acc[mi][ni][2 * h + 0] * alpha;
                    v.y = acc[mi][ni][2 * h + 1] * alpha;
                    *(float2*)(Cf + zc + (long)row * N + col) = v;
                }
            }
        }
    }

    if (MODE == MODE_SCORES) {
        __syncthreads();
        float* red_m = (float*)dynsmem;              // [2][128]
        float* red_s = (float*)(dynsmem + 1024);     // [2][128]

        float lm[4][2];
        #pragma unroll
        for (int ni = 0; ni < 4; ni++)
            #pragma unroll
            for (int cc = 0; cc < 2; cc++) {
                float m = -INFINITY;
                #pragma unroll
                for (int mi = 0; mi < 4; mi++)
                    #pragma unroll
                    for (int h = 0; h < 2; h++)
                        m = fmaxf(m, acc[mi][ni][2 * h + cc] * alpha);
                lm[ni][cc] = m;
            }
        #pragma unroll
        for (int off = 4; off < 32; off <<= 1)
            #pragma unroll
            for (int ni = 0; ni < 4; ni++)
                #pragma unroll
                for (int cc = 0; cc < 2; cc++)
                    lm[ni][cc] = fmaxf(lm[ni][cc],
                        __shfl_xor_sync(0xffffffffu, lm[ni][cc], off));
        if (lane < 4) {
            #pragma unroll
            for (int ni = 0; ni < 4; ni++)
                #pragma unroll
                for (int cc = 0; cc < 2; cc++)
                    red_m[warp_m * 128 + warp_n * 32 + ni * 8 + 2 * lane + cc] = lm[ni][cc];
        }
        __syncthreads();

        float cmax[4][2], lsum[4][2];
        #pragma unroll
        for (int ni = 0; ni < 4; ni++)
            #pragma unroll
            for (int cc = 0; cc < 2; cc++) {
                const int cl = warp_n * 32 + ni * 8 + ecol + cc;
                cmax[ni][cc] = fmaxf(red_m[cl], red_m[128 + cl]);
                float s = 0.f;
                #pragma unroll
                for (int mi = 0; mi < 4; mi++)
                    #pragma unroll
                    for (int h = 0; h < 2; h++)
                        s += __expf(acc[mi][ni][2 * h + cc] * alpha - cmax[ni][cc]);
                lsum[ni][cc] = s;
            }
        #pragma unroll
        for (int off = 4; off < 32; off <<= 1)
            #pragma unroll
            for (int ni = 0; ni < 4; ni++)
                #pragma unroll
                for (int cc = 0; cc < 2; cc++)
                    lsum[ni][cc] += __shfl_xor_sync(0xffffffffu, lsum[ni][cc], off);
        if (lane < 4) {
            #pragma unroll
            for (int ni = 0; ni < 4; ni++)
                #pragma unroll
                for (int cc = 0; cc < 2; cc++)
                    red_s[warp_m * 128 + warp_n * 32 + ni * 8 + 2 * lane + cc] = lsum[ni][cc];
        }
        __syncthreads();

        if (warp_m == 0 && lane < 4) {
            const long pbase = ((long)blockIdx.z * ICH + blockIdx.y) * SEQ + bn;
            #pragma unroll
            for (int ni = 0; ni < 4; ni++)
                #pragma unroll
                for (int cc = 0; cc < 2; cc++) {
                    const int cl = warp_n * 32 + ni * 8 + 2 * lane + cc;
                    pm[pbase + cl] = cmax[ni][cc];
                    ps[pbase + cl] = red_s[cl] + red_s[128 + cl];
                }
        }
    }
}

// ---------------------------------------------------------------------------
// x fp32 -> split panels (4 elems per thread, same 16B chunk)
// ---------------------------------------------------------------------------
__global__ void split_x(const float* __restrict__ src, bf16* __restrict__ dst)
{
    const long i = (long)blockIdx.x * blockDim.x + threadIdx.x;
    const long e4 = i * 4;
    const int row = (int)(e4 >> 9);
    const int k = (int)(e4 & 511);
    float4 a = ((const float4*)src)[i];
    bf162 h0 = __floats2bfloat162_rn(a.x, a.y);
    bf162 h1 = __floats2bfloat162_rn(a.z, a.w);
    float2 f0 = __bfloat1622float2(h0);
    float2 f1 = __bfloat1622float2(h1);
    bf162 l0 = __floats2bfloat162_rn(a.x - f0.x, a.y - f0.y);
    bf162 l1 = __floats2bfloat162_rn(a.z - f1.x, a.w - f1.y);
    const long pnl = (long)(row >> 7) * 16 + (k >> 5);
    const int r = row & 127, kk = k & 31;
    char* base = (char*)dst + (pnl << 14);
    union { bf162 v[2]; uint2 u; } uh, ul;
    uh.v[0] = h0; uh.v[1] = h1;
    ul.v[0] = l0; ul.v[1] = l1;
    *(uint2*)(base + off_hi(r, kk)) = uh.u;
    *(uint2*)(base + off_lo(r, kk)) = ul.u;
}

// ---------------------------------------------------------------------------
// W fp32 [K][N] -> Wt split panels [n][k]; grid.z selects W
// ---------------------------------------------------------------------------
__global__ void transpose_split_w(const float* __restrict__ W0,
                                  const float* __restrict__ W1,
                                  const float* __restrict__ W2,
                                  bf16* __restrict__ T)
{
    __shared__ float tile[32][33];
    const int w = blockIdx.z;
    const float* W = (w == 0) ? W0 : (w == 1) ? W1 : W2;
    const int k0 = blockIdx.y * 32, n0 = blockIdx.x * 32;
    const int tx = threadIdx.x, ty = threadIdx.y;
    #pragma unroll
    for (int yy = 0; yy < 32; yy += 8)
        tile[ty + yy][tx] = W[(long)(k0 + ty + yy) * DMODEL + n0 + tx];
    __syncthreads();
    #pragma unroll
    for (int yy = 0; yy < 32; yy += 8) {
        float v = tile[tx][ty + yy];
        bf16 h = __float2bfloat16_rn(v);
        bf16 l = __float2bfloat16_rn(v - __bfloat162float(h));
        const int ng = w * DMODEL + n0 + ty + yy;
        const int k = k0 + tx;
        const long pnl = (long)(ng >> 7) * 16 + (k >> 5);
        char* base = (char*)T + (pnl << 14);
        *(bf16*)(base + off_hi(ng & 127, k & 31)) = h;
        *(bf16*)(base + off_lo(ng & 127, k & 31)) = l;
    }
}

// ---------------------------------------------------------------------------
// Linear split V -> Vt panels [b][e rows][j], KC=64
// ---------------------------------------------------------------------------
__global__ void transpose_v(const bf16* __restrict__ Vhi, const bf16* __restrict__ Vlo,
                            bf16* __restrict__ Vt)
{
    __shared__ bf16 th[32][33], tl[32][33];
    const long b = blockIdx.z;
    const int e0 = blockIdx.x * 32, n0 = blockIdx.y * 32;
    const int tx = threadIdx.x, ty = threadIdx.y;
    #pragma unroll
    for (int yy = 0; yy < 32; yy += 8) {
        const long src = (b * SEQ + n0 + ty + yy) * DMODEL + e0 + tx;
        th[ty + yy][tx] = Vhi[src];
        tl[ty + yy][tx] = Vlo[src];
    }
    __syncthreads();
    char* bbase = (char*)Vt + b * ((long)DMODEL * SEQ * 4);
    #pragma unroll
    for (int yy = 0; yy < 32; yy += 8) {
        const int e = e0 + ty + yy;
        const int j = n0 + tx;
        const long pnl = (long)(e >> 7) * 64 + (j >> 5);
        char* base = bbase + (pnl << 14);
        *(bf16*)(base + off_hi(e & 127, j & 31)) = th[tx][ty + yy];
        *(bf16*)(base + off_lo(e & 127, j & 31)) = tl[tx][ty + yy];
    }
}

// ---------------------------------------------------------------------------
// Softmax combine + normalize; pass3 writes fp32 output AND W panels (KC=64)
// ---------------------------------------------------------------------------
__global__ void sm_pass2(const float* __restrict__ pm, const float* __restrict__ ps,
                         float* __restrict__ gm, float* __restrict__ gi)
{
    const int j = blockIdx.x * blockDim.x + threadIdx.x;
    const long b = blockIdx.y;
    float m = -INFINITY;
    #pragma unroll
    for (int ic = 0; ic < ICH; ic++)
        m = fmaxf(m, pm[(b * ICH + ic) * SEQ + j]);
    float s = 0.0f;
    #pragma unroll
    for (int ic = 0; ic < ICH; ic++)
        s += ps[(b * ICH + ic) * SEQ + j] * __expf(pm[(b * ICH + ic) * SEQ + j] - m);
    gm[b * SEQ + j] = m;
    gi[b * SEQ + j] = 1.0f / s;
}

__global__ void sm_pass3(float* __restrict__ S,
                         const float* __restrict__ gm, const float* __restrict__ gi,
                         bf16* __restrict__ Wp)
{
    const int j4 = (blockIdx.x * blockDim.x + threadIdx.x) * 4;
    const int i = blockIdx.y;
    const long b = blockIdx.z;
    const long off = b * (long)SEQ * SEQ + (long)i * SEQ + j4;
    float4 x = *(const float4*)(S + off);
    float4 m = *(const float4*)(gm + b * SEQ + j4);
    float4 v = *(const float4*)(gi + b * SEQ + j4);
    float4 w;
    w.x = __expf(x.x - m.x) * v.x;
    w.y = __expf(x.y - m.y) * v.y;
    w.z = __expf(x.z - m.z) * v.z;
    w.w = __expf(x.w - m.w) * v.w;
    *(float4*)(S + off) = w;
    bf162 h0 = __floats2bfloat162_rn(w.x, w.y);
    bf162 h1 = __floats2bfloat162_rn(w.z, w.w);
    float2 f0 = __bfloat1622float2(h0);
    float2 f1 = __bfloat1622float2(h1);
    bf162 l0 = __floats2bfloat162_rn(w.x - f0.x, w.y - f0.y);
    bf162 l1 = __floats2bfloat162_rn(w.z - f1.x, w.w - f1.y);
    char* bbase = (char*)Wp + b * ((long)SEQ * SEQ * 4);
    const long pnl = (long)(i >> 7) * 64 + (j4 >> 5);
    char* base = bbase + (pnl << 14);
    const int r = i & 127, kk = j4 & 31;
    union { bf162 v[2]; uint2 u; } uh, ul;
    uh.v[0] = h0; uh.v[1] = h1;
    ul.v[0] = l0; ul.v[1] = l1;
    *(uint2*)(base + off_hi(r, kk)) = uh.u;
    *(uint2*)(base + off_lo(r, kk)) = ul.u;
}

// ---------------------------------------------------------------------------
// kernel_launch
// ---------------------------------------------------------------------------
extern "C" void kernel_launch(void* const* d_in, const int* in_sizes, int n_in,
                              void* d_out, int out_size)
{
    const float* x  = (const float*)d_in[0];
    const float* Wq = (const float*)d_in[1];
    const float* bq = (const float*)d_in[2];
    const float* Wk = (const float*)d_in[3];
    const float* bk = (const float*)d_in[4];
    const float* Wv = (const float*)d_in[5];
    const float* bv = (const float*)d_in[6];

    float* out     = (float*)d_out;
    float* weights = out + (long)BATCH * SEQ * DMODEL;

    bf16 *xp, *Wtp, *Qp, *Kp, *Vhi, *Vlo, *Vtp, *Wp;
    float *pm, *ps, *gm, *gi;
    cudaGetSymbolAddress((void**)&xp, g_x);
    cudaGetSymbolAddress((void**)&Wtp, g_Wt);
    cudaGetSymbolAddress((void**)&Qp, g_Q);
    cudaGetSymbolAddress((void**)&Kp, g_K);
    cudaGetSymbolAddress((void**)&Vhi, g_Vhi);
    cudaGetSymbolAddress((void**)&Vlo, g_Vlo);
    cudaGetSymbolAddress((void**)&Vtp, g_Vt);
    cudaGetSymbolAddress((void**)&Wp, g_W);
    cudaGetSymbolAddress((void**)&pm, g_pm);
    cudaGetSymbolAddress((void**)&ps, g_ps);
    cudaGetSymbolAddress((void**)&gm, g_gm);
    cudaGetSymbolAddress((void**)&gi, g_gi);

    static bool attr_set = false;
    if (!attr_set) {
        cudaFuncSetAttribute(gemm_ps<MODE_PROJ>,
                             cudaFuncAttributeMaxDynamicSharedMemorySize, DYN_SMEM);
        cudaFuncSetAttribute(gemm_ps<MODE_SCORES>,
                             cudaFuncAttributeMaxDynamicSharedMemorySize, DYN_SMEM);
        cudaFuncSetAttribute(gemm_ps<MODE_AV>,
                             cudaFuncAttributeMaxDynamicSharedMemorySize, DYN_SMEM);
        attr_set = true;
    }

    const dim3 blk(256);

    // 0) inputs -> panel layout
    split_x<<<(BATCH * SEQ * DMODEL / 4) / 256, blk>>>(x, xp);
    {
        dim3 g(16, 16, 3), b(32, 8);
        transpose_split_w<<<g, b>>>(Wq, Wk, Wv, Wtp);
    }

    // 1) fused QKV projection: A = x panels, B = Wt panels (KC = 16)
    {
        dim3 grid(3 * DMODEL / BN, (BATCH * SEQ) / BM, 1);
        gemm_ps<MODE_PROJ><<<grid, blk, DYN_SMEM>>>(
            (const char*)xp, (const char*)Wtp, 1.0f, 3 * DMODEL, DMODEL / 32,
            0, 0, 0, nullptr, nullptr, nullptr, bq, bk, bv, Qp, Kp, Vhi, Vlo);
    }

    // 1b) V -> Vt panels
    {
        dim3 g(DMODEL / 32, SEQ / 32, BATCH), b(32, 8);
        transpose_v<<<g, b>>>(Vhi, Vlo, Vtp);
    }

    // 2) scores = scale * Q @ K^T -> weights fp32 + softmax partials (KC = 16)
    {
        const float scale = 1.0f / sqrtf((float)DMODEL);
        dim3 grid(SEQ / BN, SEQ / BM, BATCH);
        gemm_ps<MODE_SCORES><<<grid, blk, DYN_SMEM>>>(
            (const char*)Qp, (const char*)Kp, scale, SEQ, DMODEL / 32,
            (long)SEQ * DMODEL * 4, (long)SEQ * DMODEL * 4, (long)SEQ * SEQ,
            weights, pm, ps, nullptr, nullptr, nullptr,
            nullptr, nullptr, nullptr, nullptr);
    }

    // 3) softmax combine + normalize (pass3 emits W panels)
    {
        dim3 g2(SEQ / 256, BATCH);
        sm_pass2<<<g2, blk>>>(pm, ps, gm, gi);
        dim3 g3(SEQ / (256 * 4), SEQ, BATCH);
        sm_pass3<<<g3, blk>>>(weights, gm, gi, Wp);
    }

    // 4) out = weights @ V: A = W panels, B = Vt panels (KC = 64)
    {
        dim3 grid(DMODEL / BN, SEQ / BM, BATCH);
        gemm_ps<MODE_AV><<<grid, blk, DYN_SMEM>>>(
            (const char*)Wp, (const char*)Vtp, 1.0f, DMODEL, SEQ / 32,
            (long)SEQ * SEQ * 4, (long)DMODEL * SEQ * 4, (long)SEQ * DMODEL,
            out, nullptr, nullptr, nullptr, nullptr, nullptr,
            nullptr, nullptr, nullptr, nullptr);
    }
}